// round 14
// baseline (speedup 1.0000x reference)
#include <cuda_runtime.h>
#include <math.h>

// Problem max sizes (N=50000, E=800000)
#define NMAX 50000
#define EMAX 800000

// ---- static device scratch (zero-initialized at module load; the
// pipeline re-zeroes cnt/tile/tilectr/easum each run in k_scatter) ----
__device__ float  g_z[NMAX * 64];      // z of current layer (z0, then z1)
__device__ float  g_h[NMAX * 64];      // h of current layer
__device__ float  g_uv[NMAX * 64];     // [u | v] per node
__device__ __align__(16) float g_hdest[64];
__device__ double g_easum[2];
__device__ float  g_eamean[2];
// CSR by dst: packed edge payload {src, perm, ea.x(bits), ea.y(bits)}
__device__ int    g_cnt[NMAX];
__device__ int    g_rowptr[NMAX + 1];
__device__ int    g_rowcur[NMAX];
__device__ int4   g_epack[EMAX];
// decoupled-lookback scan state
__device__ unsigned long long g_tile[256];
__device__ int    g_tilectr;

// leaky relu, slope 0.2 < 1:  max(t, 0.2t) == leaky(t)
__device__ __forceinline__ float lrelu(float t) { return fmaxf(t, 0.2f * t); }

// ---- packed fp32x2 helpers (Blackwell FFMA2; used in k_gemv) ----
__device__ __forceinline__ unsigned long long pack2(float a, float b) {
    unsigned long long r;
    asm("mov.b64 %0, {%1, %2};" : "=l"(r) : "f"(a), "f"(b));
    return r;
}
__device__ __forceinline__ unsigned long long fma2(unsigned long long a,
                                                   unsigned long long b,
                                                   unsigned long long c) {
    unsigned long long d;
    asm("fma.rn.f32x2 %0, %1, %2, %3;" : "=l"(d) : "l"(a), "l"(b), "l"(c));
    return d;
}
__device__ __forceinline__ unsigned long long add2(unsigned long long a,
                                                   unsigned long long b) {
    unsigned long long d;
    asm("add.rn.f32x2 %0, %1, %2;" : "=l"(d) : "l"(a), "l"(b));
    return d;
}

// 8-channel logit partial: sum_c at_c * lrelu(ex*We0_c + ey*We1_c + zd_c + zs_c)
__device__ __forceinline__ float logit8(float ex, float ey,
                                        const float4& zda, const float4& zdb,
                                        const float4& zsa, const float4& zsb,
                                        const float4& We0a, const float4& We0b,
                                        const float4& We1a, const float4& We1b,
                                        const float4& ata, const float4& atb) {
    float t, p;
    t = lrelu(fmaf(ex, We0a.x, fmaf(ey, We1a.x, zda.x + zsa.x))); p = t * ata.x;
    t = lrelu(fmaf(ex, We0a.y, fmaf(ey, We1a.y, zda.y + zsa.y))); p = fmaf(t, ata.y, p);
    t = lrelu(fmaf(ex, We0a.z, fmaf(ey, We1a.z, zda.z + zsa.z))); p = fmaf(t, ata.z, p);
    t = lrelu(fmaf(ex, We0a.w, fmaf(ey, We1a.w, zda.w + zsa.w))); p = fmaf(t, ata.w, p);
    t = lrelu(fmaf(ex, We0b.x, fmaf(ey, We1b.x, zdb.x + zsb.x))); p = fmaf(t, atb.x, p);
    t = lrelu(fmaf(ex, We0b.y, fmaf(ey, We1b.y, zdb.y + zsb.y))); p = fmaf(t, atb.y, p);
    t = lrelu(fmaf(ex, We0b.z, fmaf(ey, We1b.z, zdb.z + zsb.z))); p = fmaf(t, atb.z, p);
    t = lrelu(fmaf(ex, We0b.w, fmaf(ey, We1b.w, zdb.w + zsb.w))); p = fmaf(t, atb.w, p);
    return p;
}

// ============================================================
// 0) fused: edge_attr column sums + dst histogram (blocks [0,512))
//    + vectorized z0 = x@W0+b0 (blocks [512, 512+gN8))
// ============================================================
__global__ void k_easum_hist_z0(const int* __restrict__ ei,
                                const float2* __restrict__ ea,
                                const float2* __restrict__ x,
                                const float* __restrict__ W0,
                                const float* __restrict__ b0,
                                int N, int E) {
    if (blockIdx.x < 512) {
        double d0 = 0.0, d1 = 0.0;
        for (int i = blockIdx.x * 256 + threadIdx.x; i < E; i += 512 * 256) {
            float2 v = ea[i];
            d0 += (double)v.x; d1 += (double)v.y;
            atomicAdd(&g_cnt[ei[E + i]], 1);
        }
        __shared__ double sh0[256], sh1[256];
        int t = threadIdx.x;
        sh0[t] = d0; sh1[t] = d1;
        __syncthreads();
        for (int ofs = 128; ofs > 0; ofs >>= 1) {
            if (t < ofs) { sh0[t] += sh0[t + ofs]; sh1[t] += sh1[t + ofs]; }
            __syncthreads();
        }
        if (t == 0) {
            atomicAdd(&g_easum[0], sh0[0]);
            atomicAdd(&g_easum[1], sh1[0]);
        }
    } else {
        int i = (blockIdx.x - 512) * 256 + threadIdx.x;   // [0, N*8)
        if (i < N * 8) {
            int n = i >> 3, j = (i & 7) * 8;
            float2 xv = x[n];
            float4 w0a = *(const float4*)&W0[j];
            float4 w0b = *(const float4*)&W0[j + 4];
            float4 w1a = *(const float4*)&W0[64 + j];
            float4 w1b = *(const float4*)&W0[64 + j + 4];
            float4 ba  = *(const float4*)&b0[j];
            float4 bb  = *(const float4*)&b0[j + 4];
            float4 r0, r1;
            r0.x = fmaf(xv.x, w0a.x, fmaf(xv.y, w1a.x, ba.x));
            r0.y = fmaf(xv.x, w0a.y, fmaf(xv.y, w1a.y, ba.y));
            r0.z = fmaf(xv.x, w0a.z, fmaf(xv.y, w1a.z, ba.z));
            r0.w = fmaf(xv.x, w0a.w, fmaf(xv.y, w1a.w, ba.w));
            r1.x = fmaf(xv.x, w0b.x, fmaf(xv.y, w1b.x, bb.x));
            r1.y = fmaf(xv.x, w0b.y, fmaf(xv.y, w1b.y, bb.y));
            r1.z = fmaf(xv.x, w0b.z, fmaf(xv.y, w1b.z, bb.z));
            r1.w = fmaf(xv.x, w0b.w, fmaf(xv.y, w1b.w, bb.w));
            *(float4*)&g_z[n * 64 + j]     = r0;
            *(float4*)&g_z[n * 64 + j + 4] = r1;
        }
    }
}

// ============================================================
// 1) exclusive scan of g_cnt (decoupled lookback) + eamean
// ============================================================
__global__ void __launch_bounds__(256) k_scan(int N, int E) {
    __shared__ int sbid;
    __shared__ int swsum[8];
    __shared__ int sexcl;
    if (threadIdx.x == 0) sbid = atomicAdd(&g_tilectr, 1);
    __syncthreads();
    int bid = sbid;
    if (bid == 0 && threadIdx.x < 2)
        g_eamean[threadIdx.x] = (float)(g_easum[threadIdx.x] / (double)E);

    int i = bid * 256 + threadIdx.x;
    int v = (i < N) ? g_cnt[i] : 0;
    int lane = threadIdx.x & 31, w = threadIdx.x >> 5;
    int s = v;
#pragma unroll
    for (int o = 1; o < 32; o <<= 1) {
        int t = __shfl_up_sync(0xffffffffu, s, o);
        if (lane >= o) s += t;
    }
    if (lane == 31) swsum[w] = s;
    __syncthreads();
    if (w == 0) {
        int ws = (lane < 8) ? swsum[lane] : 0;
#pragma unroll
        for (int o = 1; o < 8; o <<= 1) {
            int t = __shfl_up_sync(0xffffffffu, ws, o);
            if (lane >= o) ws += t;
        }
        if (lane < 8) swsum[lane] = ws;
    }
    __syncthreads();
    int incl = s + (w > 0 ? swsum[w - 1] : 0);
    int btotal = swsum[7];

    if (threadIdx.x == 0) {
        unsigned long long word = (bid == 0)
            ? ((2ull << 32) | (unsigned)btotal)
            : ((1ull << 32) | (unsigned)btotal);
        atomicExch(&g_tile[bid], word);
    }

    if (bid > 0 && w == 0) {
        int excl = 0;
        int look = bid - 1 - lane;
        for (;;) {
            unsigned long long word = (look >= 0)
                ? atomicAdd(&g_tile[look], 0ull) : (2ull << 32);
            unsigned st = (unsigned)(word >> 32);
            unsigned pend = __ballot_sync(0xffffffffu, st == 0u);
            if (pend) continue;
            unsigned pre = __ballot_sync(0xffffffffu, st == 2u);
            int fp = __ffs(pre) - 1;
            int val = (int)(word & 0xffffffffu);
            if (fp >= 0) {
                int contrib = (lane <= fp && look >= 0) ? val : 0;
#pragma unroll
                for (int o = 16; o > 0; o >>= 1)
                    contrib += __shfl_xor_sync(0xffffffffu, contrib, o);
                excl += contrib;
                break;
            } else {
                int contrib = (look >= 0) ? val : 0;
#pragma unroll
                for (int o = 16; o > 0; o >>= 1)
                    contrib += __shfl_xor_sync(0xffffffffu, contrib, o);
                excl += contrib;
                look -= 32;
            }
        }
        if (lane == 0) {
            atomicExch(&g_tile[bid], (2ull << 32) | (unsigned)(excl + btotal));
            sexcl = excl;
        }
    } else if (threadIdx.x == 0) {
        sexcl = 0;
    }
    __syncthreads();
    int excl = sexcl;
    if (i < N) {
        int ip = excl + incl;
        g_rowptr[i + 1] = ip;
        g_rowcur[i] = ip - v;
    }
    if (i == 0) g_rowptr[0] = 0;
}

// ============================================================
// 2) packed CSR scatter (blocks [0,gE)) + re-zero state (rest)
// ============================================================
__global__ void k_scatter(const int* __restrict__ ei,
                          const float2* __restrict__ ea,
                          int N, int E, int gE) {
    if ((int)blockIdx.x < gE) {
        int e = blockIdx.x * 256 + threadIdx.x;
        if (e < E) {
            int dst = ei[E + e];
            int pos = atomicAdd(&g_rowcur[dst], 1);
            float2 a = ea[e];
            g_epack[pos] = make_int4(ei[e], e, __float_as_int(a.x),
                                     __float_as_int(a.y));
        }
    } else {
        int i = (blockIdx.x - gE) * 256 + threadIdx.x;
        if (i < N) g_cnt[i] = 0;
        if (i < 256) g_tile[i] = 0ull;
        if (i == 0) { g_tilectr = 0; g_easum[0] = 0.0; g_easum[1] = 0.0; }
    }
}

// ============================================================
// 3/5) GATv2 aggregation: fixed softmax reference + 8-lane-per-edge
// groups (4 edges per reduce round, 2-level shuffle) + epack
// prefetch. Warp = dst node; lane = grp*8 + l8; l8 owns channels
// 8*l8..8*l8+7 (heads split between 4-lane subgroups).
// ============================================================
__global__ void __launch_bounds__(128)
k_agg(const float* __restrict__ We, const float* __restrict__ att,
      const float* __restrict__ bias, const int* __restrict__ destp, int N) {
    int dst = (blockIdx.x * blockDim.x + threadIdx.x) >> 5;
    int lane = threadIdx.x & 31;
    if (dst >= N) return;
    int grp = lane >> 3;       // edge slot within round (0..3)
    int l8 = lane & 7;
    int ch = l8 * 8;

    float4 We0a = *(const float4*)&We[ch];
    float4 We0b = *(const float4*)&We[ch + 4];
    float4 We1a = *(const float4*)&We[64 + ch];
    float4 We1b = *(const float4*)&We[64 + ch + 4];
    float4 ata  = *(const float4*)&att[ch];
    float4 atb  = *(const float4*)&att[ch + 4];
    float4 zda  = __ldg((const float4*)&g_z[dst * 64 + ch]);
    float4 zdb  = __ldg((const float4*)&g_z[dst * 64 + ch + 4]);

    // self-loop logit = fixed softmax reference m (per head)
    float eax = g_eamean[0], eay = g_eamean[1];
    float m = logit8(eax, eay, zda, zdb, zda, zdb,
                     We0a, We0b, We1a, We1b, ata, atb);
    m += __shfl_xor_sync(0xffffffffu, m, 2);
    m += __shfl_xor_sync(0xffffffffu, m, 1);

    // self-loop contribution counted once (group 0)
    float denom = (grp == 0) ? 1.f : 0.f;
    float4 aca, acb;
    if (grp == 0) { aca = zda; acb = zdb; }
    else {
        aca = make_float4(0.f, 0.f, 0.f, 0.f);
        acb = aca;
    }

    int idx = g_rowptr[dst], end = g_rowptr[dst + 1];

    // prologue: prefetch first epack pair
    int4 pA, pB;
    if (idx + 8 <= end) {
        pA = g_epack[idx + grp];
        pB = g_epack[idx + 4 + grp];
    }
    while (idx + 8 <= end) {
        float4 zAa = __ldg((const float4*)&g_z[pA.x * 64 + ch]);
        float4 zAb = __ldg((const float4*)&g_z[pA.x * 64 + ch + 4]);
        float4 zBa = __ldg((const float4*)&g_z[pB.x * 64 + ch]);
        float4 zBb = __ldg((const float4*)&g_z[pB.x * 64 + ch + 4]);
        float eAx = __int_as_float(pA.z), eAy = __int_as_float(pA.w);
        float eBx = __int_as_float(pB.z), eBy = __int_as_float(pB.w);
        idx += 8;
        int4 nA, nB;
        if (idx + 8 <= end) {
            nA = g_epack[idx + grp];
            nB = g_epack[idx + 4 + grp];
        }

        float pa = logit8(eAx, eAy, zda, zdb, zAa, zAb,
                          We0a, We0b, We1a, We1b, ata, atb);
        float pb = logit8(eBx, eBy, zda, zdb, zBa, zBb,
                          We0a, We0b, We1a, We1b, ata, atb);
        pa += __shfl_xor_sync(0xffffffffu, pa, 2);
        pb += __shfl_xor_sync(0xffffffffu, pb, 2);
        pa += __shfl_xor_sync(0xffffffffu, pa, 1);
        pb += __shfl_xor_sync(0xffffffffu, pb, 1);
        float wa = __expf(pa - m);
        float wb = __expf(pb - m);
        denom += wa + wb;
        aca.x = fmaf(wa, zAa.x, aca.x); aca.x = fmaf(wb, zBa.x, aca.x);
        aca.y = fmaf(wa, zAa.y, aca.y); aca.y = fmaf(wb, zBa.y, aca.y);
        aca.z = fmaf(wa, zAa.z, aca.z); aca.z = fmaf(wb, zBa.z, aca.z);
        aca.w = fmaf(wa, zAa.w, aca.w); aca.w = fmaf(wb, zBa.w, aca.w);
        acb.x = fmaf(wa, zAb.x, acb.x); acb.x = fmaf(wb, zBb.x, acb.x);
        acb.y = fmaf(wa, zAb.y, acb.y); acb.y = fmaf(wb, zBb.y, acb.y);
        acb.z = fmaf(wa, zAb.z, acb.z); acb.z = fmaf(wb, zBb.z, acb.z);
        acb.w = fmaf(wa, zAb.w, acb.w); acb.w = fmaf(wb, zBb.w, acb.w);
        pA = nA; pB = nB;
    }
    // tail: 4 edges at a time with validity guard
    for (; idx < end; idx += 4) {
        int e = idx + grp;
        bool valid = e < end;
        int4 pR = g_epack[valid ? e : (end - 1)];
        float4 zAa = __ldg((const float4*)&g_z[pR.x * 64 + ch]);
        float4 zAb = __ldg((const float4*)&g_z[pR.x * 64 + ch + 4]);
        float eAx = __int_as_float(pR.z), eAy = __int_as_float(pR.w);
        float pa = logit8(eAx, eAy, zda, zdb, zAa, zAb,
                          We0a, We0b, We1a, We1b, ata, atb);
        pa += __shfl_xor_sync(0xffffffffu, pa, 2);
        pa += __shfl_xor_sync(0xffffffffu, pa, 1);
        float wa = valid ? __expf(pa - m) : 0.f;
        denom += wa;
        aca.x = fmaf(wa, zAa.x, aca.x);
        aca.y = fmaf(wa, zAa.y, aca.y);
        aca.z = fmaf(wa, zAa.z, aca.z);
        aca.w = fmaf(wa, zAa.w, aca.w);
        acb.x = fmaf(wa, zAb.x, acb.x);
        acb.y = fmaf(wa, zAb.y, acb.y);
        acb.z = fmaf(wa, zAb.z, acb.z);
        acb.w = fmaf(wa, zAb.w, acb.w);
    }
    // merge the 4 groups (shared per-head m -> plain addition)
#define MRG8(v) v += __shfl_xor_sync(0xffffffffu, v, 8); \
                v += __shfl_xor_sync(0xffffffffu, v, 16);
    MRG8(denom);
    MRG8(aca.x); MRG8(aca.y); MRG8(aca.z); MRG8(aca.w);
    MRG8(acb.x); MRG8(acb.y); MRG8(acb.z); MRG8(acb.w);
#undef MRG8

    if (grp == 0) {
        float inv = __fdividef(1.f, denom + 1e-16f);
        float4 b4a = *(const float4*)&bias[ch];
        float4 b4b = *(const float4*)&bias[ch + 4];
        float o; float4 ha, hb;
        o = fmaf(aca.x, inv, b4a.x); ha.x = (o > 0.f) ? o : expm1f(o);
        o = fmaf(aca.y, inv, b4a.y); ha.y = (o > 0.f) ? o : expm1f(o);
        o = fmaf(aca.z, inv, b4a.z); ha.z = (o > 0.f) ? o : expm1f(o);
        o = fmaf(aca.w, inv, b4a.w); ha.w = (o > 0.f) ? o : expm1f(o);
        o = fmaf(acb.x, inv, b4b.x); hb.x = (o > 0.f) ? o : expm1f(o);
        o = fmaf(acb.y, inv, b4b.y); hb.y = (o > 0.f) ? o : expm1f(o);
        o = fmaf(acb.z, inv, b4b.z); hb.z = (o > 0.f) ? o : expm1f(o);
        o = fmaf(acb.w, inv, b4b.w); hb.w = (o > 0.f) ? o : expm1f(o);
        *(float4*)&g_h[dst * 64 + ch]     = ha;
        *(float4*)&g_h[dst * 64 + ch + 4] = hb;
        if (destp && dst == destp[0]) {
            *(float4*)&g_hdest[ch]     = ha;
            *(float4*)&g_hdest[ch + 4] = hb;
        }
    }
}

// ============================================================
// 4/6) register-tiled GEMM on device globals:
// mode 0: g_z[N,64]  = g_h[N,64] @ W (64x64 row-major) + bias
// mode 1: g_uv[N,64] = g_h[N,64] @ W' where
//         W'[k][j] = j<32 ? W[k*32+j] : W[(64+k)*32+j-32]   (no bias)
// ============================================================
__global__ void __launch_bounds__(128)
k_gemv(const float* __restrict__ W, const float* __restrict__ bias,
       int N, int mode) {
    __shared__ __align__(16) float sW[64 * 64];
    __shared__ __align__(16) float sA[64 * 68];

    for (int idx = threadIdx.x; idx < 4096; idx += 128) {
        int k = idx >> 6, j = idx & 63;
        sW[idx] = (mode == 0) ? W[idx]
                : ((j < 32) ? W[k * 32 + j] : W[(64 + k) * 32 + (j - 32)]);
    }
    int nbase = blockIdx.x * 64;
    for (int idx = threadIdx.x; idx < 64 * 16; idx += 128) {
        int n = idx >> 4, k4 = idx & 15;
        float4 av = (nbase + n < N)
            ? *(const float4*)&g_h[(nbase + n) * 64 + k4 * 4]
            : make_float4(0.f, 0.f, 0.f, 0.f);
        *(float4*)&sA[n * 68 + k4 * 4] = av;
    }
    __syncthreads();

    int cg = threadIdx.x & 7;        // channels cg*8 .. cg*8+7
    int ng = threadIdx.x >> 3;       // nodes ng*4 .. ng*4+3
    __align__(16) unsigned long long acc[4][4];
#pragma unroll
    for (int i = 0; i < 4; i++)
#pragma unroll
        for (int j = 0; j < 4; j++) acc[i][j] = 0ull;

    for (int k4 = 0; k4 < 16; k4++) {
        float4 a4[4];
#pragma unroll
        for (int i = 0; i < 4; i++)
            a4[i] = *(const float4*)&sA[(ng * 4 + i) * 68 + k4 * 4];
#pragma unroll
        for (int kk = 0; kk < 4; kk++) {
            int k = k4 * 4 + kk;
            ulonglong2 wl = *(const ulonglong2*)&sW[k * 64 + cg * 8];
            ulonglong2 wh = *(const ulonglong2*)&sW[k * 64 + cg * 8 + 4];
#pragma unroll
            for (int i = 0; i < 4; i++) {
                float a = (kk == 0) ? a4[i].x : (kk == 1) ? a4[i].y
                        : (kk == 2) ? a4[i].z : a4[i].w;
                unsigned long long aa = pack2(a, a);
                acc[i][0] = fma2(aa, wl.x, acc[i][0]);
                acc[i][1] = fma2(aa, wl.y, acc[i][1]);
                acc[i][2] = fma2(aa, wh.x, acc[i][2]);
                acc[i][3] = fma2(aa, wh.y, acc[i][3]);
            }
        }
    }
    if (mode == 0) {
        ulonglong2 b0 = *(const ulonglong2*)&bias[cg * 8];
        ulonglong2 b1v = *(const ulonglong2*)&bias[cg * 8 + 4];
#pragma unroll
        for (int i = 0; i < 4; i++) {
            acc[i][0] = add2(acc[i][0], b0.x);
            acc[i][1] = add2(acc[i][1], b0.y);
            acc[i][2] = add2(acc[i][2], b1v.x);
            acc[i][3] = add2(acc[i][3], b1v.y);
        }
    }
    float* C = (mode == 0) ? g_z : g_uv;
#pragma unroll
    for (int i = 0; i < 4; i++) {
        int n = nbase + ng * 4 + i;
        if (n < N) {
            *(float4*)&C[n * 64 + cg * 8]     = *(float4*)&acc[i][0];
            *(float4*)&C[n * 64 + cg * 8 + 4] = *(float4*)&acc[i][2];
        }
    }
}

// ============================================================
// 7) edge MLP, warp per dst node, 4 edges x 8 lanes per iteration,
// epack prefetch + nested-FMA MLP row. 128-thread blocks.
// ============================================================
__global__ void __launch_bounds__(128)
k_edge(const float* __restrict__ Wm1, const float* __restrict__ bm1,
       const float* __restrict__ Wm2, const float* __restrict__ bm2,
       float* __restrict__ out, int N) {
    __shared__ float sg[32];
    if (threadIdx.x < 32) {
        int j = threadIdx.x;
        float acc = bm1[j];
#pragma unroll
        for (int k = 0; k < 64; k++)
            acc = fmaf(g_hdest[k], Wm1[(128 + k) * 32 + j], acc);
        sg[j] = acc;
    }
    __syncthreads();

    int warp = (blockIdx.x * blockDim.x + threadIdx.x) >> 5;
    int lane = threadIdx.x & 31;
    if (warp >= N) return;
    int dst = warp;
    int g = lane >> 3;          // edge slot 0..3
    int l = lane & 7;           // channel block: channels [4l, 4l+4)

    float4 v4 = __ldg((const float4*)&g_uv[dst * 64 + 32 + l * 4]);
    float4 gv = *(const float4*)&sg[l * 4];
    float4 w0 = __ldg(&((const float4*)&Wm1[192 * 32])[l]);
    float4 w1 = __ldg(&((const float4*)&Wm1[193 * 32])[l]);
    float4 w2 = __ldg(&((const float4*)Wm2)[l]);
    float bm2v = bm2[0];
    float bx = v4.x + gv.x, by = v4.y + gv.y;
    float bz = v4.z + gv.z, bw = v4.w + gv.w;

    int start = g_rowptr[dst], end = g_rowptr[dst + 1];
    if (start >= end) return;
    int e0 = start + g;
    int4 pk = g_epack[(e0 < end) ? e0 : (end - 1)];
    for (int idx = start; idx < end; idx += 4) {
        int e = idx + g;
        bool valid = e < end;
        float4 u4 = __ldg((const float4*)&g_uv[pk.x * 64 + l * 4]);
        float ax = __int_as_float(pk.z), ay = __int_as_float(pk.w);
        int perm = pk.y;
        int en = idx + 4 + g;
        if (idx + 4 < end) pk = g_epack[(en < end) ? en : (end - 1)];

        float m0 = fmaf(ax, w0.x, fmaf(ay, w1.x, u4.x + bx));
        float m1 = fmaf(ax, w0.y, fmaf(ay, w1.y, u4.y + by));
        float m2 = fmaf(ax, w0.z, fmaf(ay, w1.z, u4.z + bz));
        float m3 = fmaf(ax, w0.w, fmaf(ay, w1.w, u4.w + bw));
        m0 = fmaxf(m0, 0.f); m1 = fmaxf(m1, 0.f);
        m2 = fmaxf(m2, 0.f); m3 = fmaxf(m3, 0.f);
        float s = fmaf(m0, w2.x, fmaf(m1, w2.y, fmaf(m2, w2.z, m3 * w2.w)));
        s += __shfl_xor_sync(0xffffffffu, s, 4);
        s += __shfl_xor_sync(0xffffffffu, s, 2);
        s += __shfl_xor_sync(0xffffffffu, s, 1);
        if (valid && l == 0) out[perm] = s + bm2v;
    }
}

// ============================================================
extern "C" void kernel_launch(void* const* d_in, const int* in_sizes, int n_in,
                              void* d_out, int out_size) {
    const float* x     = (const float*)d_in[0];
    const int*   ei    = (const int*)d_in[1];
    const float* ea    = (const float*)d_in[2];
    const int*   dest  = (const int*)d_in[3];
    const float* W0    = (const float*)d_in[4];
    const float* b0    = (const float*)d_in[5];
    const float* We0   = (const float*)d_in[6];
    const float* att0  = (const float*)d_in[7];
    const float* bias0 = (const float*)d_in[8];
    const float* W1    = (const float*)d_in[9];
    const float* b1    = (const float*)d_in[10];
    const float* We1   = (const float*)d_in[11];
    const float* att1  = (const float*)d_in[12];
    const float* bias1 = (const float*)d_in[13];
    const float* Wm1   = (const float*)d_in[14];
    const float* bm1   = (const float*)d_in[15];
    const float* Wm2   = (const float*)d_in[16];
    const float* bm2   = (const float*)d_in[17];

    int N = in_sizes[0] / 2;
    int E = in_sizes[1] / 2;

    const int TB = 256;
    int gE    = (E + TB - 1) / TB;
    int gN    = (N + TB - 1) / TB;
    int gN8   = (N * 8 + TB - 1) / TB;
    int gAgg  = (N * 32 + 127) / 128;   // 128-thread blocks, warp per dst
    int gGemv = (N + 63) / 64;
    int nSB   = (N + 255) / 256;

    k_easum_hist_z0<<<512 + gN8, TB>>>(ei, (const float2*)ea,
                                       (const float2*)x, W0, b0, N, E);  // 0
    k_scan<<<nSB, 256>>>(N, E);                                          // 1
    k_scatter<<<gE + gN, TB>>>(ei, (const float2*)ea, N, E, gE);         // 2
    // layer 0
    k_agg<<<gAgg, 128>>>(We0, att0, bias0, (const int*)0, N);            // 3 (profiled)
    k_gemv<<<gGemv, 128>>>(W1, b1, N, 0);                                // 4
    // layer 1
    k_agg<<<gAgg, 128>>>(We1, att1, bias1, dest, N);                     // 5
    k_gemv<<<gGemv, 128>>>(Wm1, (const float*)0, N, 1);                  // 6
    // edge scoring head
    k_edge<<<gAgg, 128>>>(Wm1, bm1, Wm2, bm2, (float*)d_out, N);         // 7
}

// round 15
// speedup vs baseline: 1.1981x; 1.1981x over previous
#include <cuda_runtime.h>
#include <math.h>

// Problem max sizes (N=50000, E=800000)
#define NMAX 50000
#define EMAX 800000

// ---- static device scratch (zero-initialized at module load; the
// pipeline re-zeroes cnt/tile/tilectr/easum each run in k_scatter) ----
__device__ float  g_z[NMAX * 64];      // z of current layer (z0, then z1)
__device__ float  g_h[NMAX * 64];      // h of current layer
__device__ float  g_uv[NMAX * 64];     // [u | v] per node
__device__ __align__(16) float g_hdest[64];
__device__ double g_easum[2];
__device__ float  g_eamean[2];
// CSR by dst: packed edge payload {src, perm, ea.x(bits), ea.y(bits)}
__device__ int    g_cnt[NMAX];
__device__ int    g_rowptr[NMAX + 1];
__device__ int    g_rowcur[NMAX];
__device__ int4   g_epack[EMAX];
// decoupled-lookback scan state
__device__ unsigned long long g_tile[256];
__device__ int    g_tilectr;

// leaky relu, slope 0.2 < 1:  max(t, 0.2t) == leaky(t)
__device__ __forceinline__ float lrelu(float t) { return fmaxf(t, 0.2f * t); }

// ---- packed fp32x2 helpers (Blackwell FFMA2; used in k_gemv) ----
__device__ __forceinline__ unsigned long long pack2(float a, float b) {
    unsigned long long r;
    asm("mov.b64 %0, {%1, %2};" : "=l"(r) : "f"(a), "f"(b));
    return r;
}
__device__ __forceinline__ unsigned long long fma2(unsigned long long a,
                                                   unsigned long long b,
                                                   unsigned long long c) {
    unsigned long long d;
    asm("fma.rn.f32x2 %0, %1, %2, %3;" : "=l"(d) : "l"(a), "l"(b), "l"(c));
    return d;
}
__device__ __forceinline__ unsigned long long add2(unsigned long long a,
                                                   unsigned long long b) {
    unsigned long long d;
    asm("add.rn.f32x2 %0, %1, %2;" : "=l"(d) : "l"(a), "l"(b));
    return d;
}

// ============================================================
// 0) fused: edge_attr column sums + dst histogram (blocks [0,512))
//    + vectorized z0 = x@W0+b0 (blocks [512, 512+gN8))
// ============================================================
__global__ void k_easum_hist_z0(const int* __restrict__ ei,
                                const float2* __restrict__ ea,
                                const float2* __restrict__ x,
                                const float* __restrict__ W0,
                                const float* __restrict__ b0,
                                int N, int E) {
    if (blockIdx.x < 512) {
        double d0 = 0.0, d1 = 0.0;
        for (int i = blockIdx.x * 256 + threadIdx.x; i < E; i += 512 * 256) {
            float2 v = ea[i];
            d0 += (double)v.x; d1 += (double)v.y;
            atomicAdd(&g_cnt[ei[E + i]], 1);
        }
        __shared__ double sh0[256], sh1[256];
        int t = threadIdx.x;
        sh0[t] = d0; sh1[t] = d1;
        __syncthreads();
        for (int ofs = 128; ofs > 0; ofs >>= 1) {
            if (t < ofs) { sh0[t] += sh0[t + ofs]; sh1[t] += sh1[t + ofs]; }
            __syncthreads();
        }
        if (t == 0) {
            atomicAdd(&g_easum[0], sh0[0]);
            atomicAdd(&g_easum[1], sh1[0]);
        }
    } else {
        int i = (blockIdx.x - 512) * 256 + threadIdx.x;   // [0, N*8)
        if (i < N * 8) {
            int n = i >> 3, j = (i & 7) * 8;
            float2 xv = x[n];
            float4 w0a = *(const float4*)&W0[j];
            float4 w0b = *(const float4*)&W0[j + 4];
            float4 w1a = *(const float4*)&W0[64 + j];
            float4 w1b = *(const float4*)&W0[64 + j + 4];
            float4 ba  = *(const float4*)&b0[j];
            float4 bb  = *(const float4*)&b0[j + 4];
            float4 r0, r1;
            r0.x = fmaf(xv.x, w0a.x, fmaf(xv.y, w1a.x, ba.x));
            r0.y = fmaf(xv.x, w0a.y, fmaf(xv.y, w1a.y, ba.y));
            r0.z = fmaf(xv.x, w0a.z, fmaf(xv.y, w1a.z, ba.z));
            r0.w = fmaf(xv.x, w0a.w, fmaf(xv.y, w1a.w, ba.w));
            r1.x = fmaf(xv.x, w0b.x, fmaf(xv.y, w1b.x, bb.x));
            r1.y = fmaf(xv.x, w0b.y, fmaf(xv.y, w1b.y, bb.y));
            r1.z = fmaf(xv.x, w0b.z, fmaf(xv.y, w1b.z, bb.z));
            r1.w = fmaf(xv.x, w0b.w, fmaf(xv.y, w1b.w, bb.w));
            *(float4*)&g_z[n * 64 + j]     = r0;
            *(float4*)&g_z[n * 64 + j + 4] = r1;
        }
    }
}

// ============================================================
// 1) exclusive scan of g_cnt (decoupled lookback) + eamean
// ============================================================
__global__ void __launch_bounds__(256) k_scan(int N, int E) {
    __shared__ int sbid;
    __shared__ int swsum[8];
    __shared__ int sexcl;
    if (threadIdx.x == 0) sbid = atomicAdd(&g_tilectr, 1);
    __syncthreads();
    int bid = sbid;
    if (bid == 0 && threadIdx.x < 2)
        g_eamean[threadIdx.x] = (float)(g_easum[threadIdx.x] / (double)E);

    int i = bid * 256 + threadIdx.x;
    int v = (i < N) ? g_cnt[i] : 0;
    int lane = threadIdx.x & 31, w = threadIdx.x >> 5;
    int s = v;
#pragma unroll
    for (int o = 1; o < 32; o <<= 1) {
        int t = __shfl_up_sync(0xffffffffu, s, o);
        if (lane >= o) s += t;
    }
    if (lane == 31) swsum[w] = s;
    __syncthreads();
    if (w == 0) {
        int ws = (lane < 8) ? swsum[lane] : 0;
#pragma unroll
        for (int o = 1; o < 8; o <<= 1) {
            int t = __shfl_up_sync(0xffffffffu, ws, o);
            if (lane >= o) ws += t;
        }
        if (lane < 8) swsum[lane] = ws;
    }
    __syncthreads();
    int incl = s + (w > 0 ? swsum[w - 1] : 0);
    int btotal = swsum[7];

    if (threadIdx.x == 0) {
        unsigned long long word = (bid == 0)
            ? ((2ull << 32) | (unsigned)btotal)
            : ((1ull << 32) | (unsigned)btotal);
        atomicExch(&g_tile[bid], word);
    }

    if (bid > 0 && w == 0) {
        int excl = 0;
        int look = bid - 1 - lane;
        for (;;) {
            unsigned long long word = (look >= 0)
                ? atomicAdd(&g_tile[look], 0ull) : (2ull << 32);
            unsigned st = (unsigned)(word >> 32);
            unsigned pend = __ballot_sync(0xffffffffu, st == 0u);
            if (pend) continue;
            unsigned pre = __ballot_sync(0xffffffffu, st == 2u);
            int fp = __ffs(pre) - 1;
            int val = (int)(word & 0xffffffffu);
            if (fp >= 0) {
                int contrib = (lane <= fp && look >= 0) ? val : 0;
#pragma unroll
                for (int o = 16; o > 0; o >>= 1)
                    contrib += __shfl_xor_sync(0xffffffffu, contrib, o);
                excl += contrib;
                break;
            } else {
                int contrib = (look >= 0) ? val : 0;
#pragma unroll
                for (int o = 16; o > 0; o >>= 1)
                    contrib += __shfl_xor_sync(0xffffffffu, contrib, o);
                excl += contrib;
                look -= 32;
            }
        }
        if (lane == 0) {
            atomicExch(&g_tile[bid], (2ull << 32) | (unsigned)(excl + btotal));
            sexcl = excl;
        }
    } else if (threadIdx.x == 0) {
        sexcl = 0;
    }
    __syncthreads();
    int excl = sexcl;
    if (i < N) {
        int ip = excl + incl;
        g_rowptr[i + 1] = ip;
        g_rowcur[i] = ip - v;
    }
    if (i == 0) g_rowptr[0] = 0;
}

// ============================================================
// 2) packed CSR scatter (blocks [0,gE)) + re-zero state (rest)
// ============================================================
__global__ void k_scatter(const int* __restrict__ ei,
                          const float2* __restrict__ ea,
                          int N, int E, int gE) {
    if ((int)blockIdx.x < gE) {
        int e = blockIdx.x * 256 + threadIdx.x;
        if (e < E) {
            int dst = ei[E + e];
            int pos = atomicAdd(&g_rowcur[dst], 1);
            float2 a = ea[e];
            g_epack[pos] = make_int4(ei[e], e, __float_as_int(a.x),
                                     __float_as_int(a.y));
        }
    } else {
        int i = (blockIdx.x - gE) * 256 + threadIdx.x;
        if (i < N) g_cnt[i] = 0;
        if (i < 256) g_tile[i] = 0ull;
        if (i == 0) { g_tilectr = 0; g_easum[0] = 0.0; g_easum[1] = 0.0; }
    }
}

// ============================================================
// 3/5) GATv2 aggregation (R13 form — best measured): fixed softmax
// reference + half-warp edge parallelism + epack prefetch +
// nested-FMA logits + FMNMX leaky. 128-thread blocks.
// ============================================================
__global__ void __launch_bounds__(128)
k_agg(const float* __restrict__ We, const float* __restrict__ att,
      const float* __restrict__ bias, const int* __restrict__ destp, int N) {
    int dst = (blockIdx.x * blockDim.x + threadIdx.x) >> 5;
    int lane = threadIdx.x & 31;
    if (dst >= N) return;
    int half = lane >> 4;
    int q = lane & 15;
    int ch = q * 4;

    float4 We0 = *(const float4*)&We[ch];
    float4 We1 = *(const float4*)&We[64 + ch];
    float4 at  = *(const float4*)&att[ch];
    float4 zd  = __ldg((const float4*)&g_z[dst * 64 + ch]);

    // self-loop logit = fixed softmax reference m
    float eax = g_eamean[0], eay = g_eamean[1];
    float t, m;
    t = lrelu(fmaf(eax, We0.x, fmaf(eay, We1.x, zd.x + zd.x))); m = t * at.x;
    t = lrelu(fmaf(eax, We0.y, fmaf(eay, We1.y, zd.y + zd.y))); m = fmaf(t, at.y, m);
    t = lrelu(fmaf(eax, We0.z, fmaf(eay, We1.z, zd.z + zd.z))); m = fmaf(t, at.z, m);
    t = lrelu(fmaf(eax, We0.w, fmaf(eay, We1.w, zd.w + zd.w))); m = fmaf(t, at.w, m);
#pragma unroll
    for (int o = 4; o >= 1; o >>= 1) m += __shfl_xor_sync(0xffffffffu, m, o);

    float denom = (half == 0) ? 1.f : 0.f;
    float4 acc;
    acc.x = (half == 0) ? zd.x : 0.f;
    acc.y = (half == 0) ? zd.y : 0.f;
    acc.z = (half == 0) ? zd.z : 0.f;
    acc.w = (half == 0) ? zd.w : 0.f;

    int idx = g_rowptr[dst], end = g_rowptr[dst + 1];

    // prologue: prefetch first epack quad
    int4 pA, pB;
    if (idx + 4 <= end) {
        pA = g_epack[idx + half];
        pB = g_epack[idx + 2 + half];
    }
    while (idx + 4 <= end) {
        float4 zA = __ldg((const float4*)&g_z[pA.x * 64 + ch]);
        float4 zB = __ldg((const float4*)&g_z[pB.x * 64 + ch]);
        float eAx = __int_as_float(pA.z), eAy = __int_as_float(pA.w);
        float eBx = __int_as_float(pB.z), eBy = __int_as_float(pB.w);
        idx += 4;
        int4 nA, nB;
        if (idx + 4 <= end) {
            nA = g_epack[idx + half];
            nB = g_epack[idx + 2 + half];
        }

        float pa, pb;
        t = lrelu(fmaf(eAx, We0.x, fmaf(eAy, We1.x, zd.x + zA.x))); pa = t * at.x;
        t = lrelu(fmaf(eAx, We0.y, fmaf(eAy, We1.y, zd.y + zA.y))); pa = fmaf(t, at.y, pa);
        t = lrelu(fmaf(eAx, We0.z, fmaf(eAy, We1.z, zd.z + zA.z))); pa = fmaf(t, at.z, pa);
        t = lrelu(fmaf(eAx, We0.w, fmaf(eAy, We1.w, zd.w + zA.w))); pa = fmaf(t, at.w, pa);

        t = lrelu(fmaf(eBx, We0.x, fmaf(eBy, We1.x, zd.x + zB.x))); pb = t * at.x;
        t = lrelu(fmaf(eBx, We0.y, fmaf(eBy, We1.y, zd.y + zB.y))); pb = fmaf(t, at.y, pb);
        t = lrelu(fmaf(eBx, We0.z, fmaf(eBy, We1.z, zd.z + zB.z))); pb = fmaf(t, at.z, pb);
        t = lrelu(fmaf(eBx, We0.w, fmaf(eBy, We1.w, zd.w + zB.w))); pb = fmaf(t, at.w, pb);

#pragma unroll
        for (int o = 4; o >= 1; o >>= 1) {
            pa += __shfl_xor_sync(0xffffffffu, pa, o);
            pb += __shfl_xor_sync(0xffffffffu, pb, o);
        }
        float wa = __expf(pa - m);
        float wb = __expf(pb - m);
        denom += wa + wb;
        acc.x = fmaf(wa, zA.x, acc.x); acc.x = fmaf(wb, zB.x, acc.x);
        acc.y = fmaf(wa, zA.y, acc.y); acc.y = fmaf(wb, zB.y, acc.y);
        acc.z = fmaf(wa, zA.z, acc.z); acc.z = fmaf(wb, zB.z, acc.z);
        acc.w = fmaf(wa, zA.w, acc.w); acc.w = fmaf(wb, zB.w, acc.w);
        pA = nA; pB = nB;
    }
    // remainder: up to 3 edges, 2 at a time with validity guard
    for (; idx < end; idx += 2) {
        int e = idx + half;
        bool valid = e < end;
        int4 pR = g_epack[valid ? e : (end - 1)];
        float4 zA = __ldg((const float4*)&g_z[pR.x * 64 + ch]);
        float eAx = __int_as_float(pR.z), eAy = __int_as_float(pR.w);
        float pa;
        t = lrelu(fmaf(eAx, We0.x, fmaf(eAy, We1.x, zd.x + zA.x))); pa = t * at.x;
        t = lrelu(fmaf(eAx, We0.y, fmaf(eAy, We1.y, zd.y + zA.y))); pa = fmaf(t, at.y, pa);
        t = lrelu(fmaf(eAx, We0.z, fmaf(eAy, We1.z, zd.z + zA.z))); pa = fmaf(t, at.z, pa);
        t = lrelu(fmaf(eAx, We0.w, fmaf(eAy, We1.w, zd.w + zA.w))); pa = fmaf(t, at.w, pa);
#pragma unroll
        for (int o = 4; o >= 1; o >>= 1) pa += __shfl_xor_sync(0xffffffffu, pa, o);
        float wa = valid ? __expf(pa - m) : 0.f;
        denom += wa;
        acc.x = fmaf(wa, zA.x, acc.x);
        acc.y = fmaf(wa, zA.y, acc.y);
        acc.z = fmaf(wa, zA.z, acc.z);
        acc.w = fmaf(wa, zA.w, acc.w);
    }
    // merge half-warps (shared m -> plain addition)
    denom += __shfl_xor_sync(0xffffffffu, denom, 16);
    acc.x += __shfl_xor_sync(0xffffffffu, acc.x, 16);
    acc.y += __shfl_xor_sync(0xffffffffu, acc.y, 16);
    acc.z += __shfl_xor_sync(0xffffffffu, acc.z, 16);
    acc.w += __shfl_xor_sync(0xffffffffu, acc.w, 16);

    if (half == 0) {
        float inv = __fdividef(1.f, denom + 1e-16f);
        float4 b4 = *(const float4*)&bias[ch];
        float o; float4 h;
        o = fmaf(acc.x, inv, b4.x); h.x = (o > 0.f) ? o : expm1f(o);
        o = fmaf(acc.y, inv, b4.y); h.y = (o > 0.f) ? o : expm1f(o);
        o = fmaf(acc.z, inv, b4.z); h.z = (o > 0.f) ? o : expm1f(o);
        o = fmaf(acc.w, inv, b4.w); h.w = (o > 0.f) ? o : expm1f(o);
        *(float4*)&g_h[dst * 64 + ch] = h;
        if (destp && dst == destp[0]) *(float4*)&g_hdest[ch] = h;
    }
}

// ============================================================
// 4/6) register-tiled GEMM on device globals:
// mode 0: g_z[N,64]  = g_h[N,64] @ W (64x64 row-major) + bias
// mode 1: g_uv[N,64] = g_h[N,64] @ W' where
//         W'[k][j] = j<32 ? W[k*32+j] : W[(64+k)*32+j-32]   (no bias)
// ============================================================
__global__ void __launch_bounds__(128)
k_gemv(const float* __restrict__ W, const float* __restrict__ bias,
       int N, int mode) {
    __shared__ __align__(16) float sW[64 * 64];
    __shared__ __align__(16) float sA[64 * 68];

    for (int idx = threadIdx.x; idx < 4096; idx += 128) {
        int k = idx >> 6, j = idx & 63;
        sW[idx] = (mode == 0) ? W[idx]
                : ((j < 32) ? W[k * 32 + j] : W[(64 + k) * 32 + (j - 32)]);
    }
    int nbase = blockIdx.x * 64;
    for (int idx = threadIdx.x; idx < 64 * 16; idx += 128) {
        int n = idx >> 4, k4 = idx & 15;
        float4 av = (nbase + n < N)
            ? *(const float4*)&g_h[(nbase + n) * 64 + k4 * 4]
            : make_float4(0.f, 0.f, 0.f, 0.f);
        *(float4*)&sA[n * 68 + k4 * 4] = av;
    }
    __syncthreads();

    int cg = threadIdx.x & 7;        // channels cg*8 .. cg*8+7
    int ng = threadIdx.x >> 3;       // nodes ng*4 .. ng*4+3
    __align__(16) unsigned long long acc[4][4];
#pragma unroll
    for (int i = 0; i < 4; i++)
#pragma unroll
        for (int j = 0; j < 4; j++) acc[i][j] = 0ull;

    for (int k4 = 0; k4 < 16; k4++) {
        float4 a4[4];
#pragma unroll
        for (int i = 0; i < 4; i++)
            a4[i] = *(const float4*)&sA[(ng * 4 + i) * 68 + k4 * 4];
#pragma unroll
        for (int kk = 0; kk < 4; kk++) {
            int k = k4 * 4 + kk;
            ulonglong2 wl = *(const ulonglong2*)&sW[k * 64 + cg * 8];
            ulonglong2 wh = *(const ulonglong2*)&sW[k * 64 + cg * 8 + 4];
#pragma unroll
            for (int i = 0; i < 4; i++) {
                float a = (kk == 0) ? a4[i].x : (kk == 1) ? a4[i].y
                        : (kk == 2) ? a4[i].z : a4[i].w;
                unsigned long long aa = pack2(a, a);
                acc[i][0] = fma2(aa, wl.x, acc[i][0]);
                acc[i][1] = fma2(aa, wl.y, acc[i][1]);
                acc[i][2] = fma2(aa, wh.x, acc[i][2]);
                acc[i][3] = fma2(aa, wh.y, acc[i][3]);
            }
        }
    }
    if (mode == 0) {
        ulonglong2 b0 = *(const ulonglong2*)&bias[cg * 8];
        ulonglong2 b1v = *(const ulonglong2*)&bias[cg * 8 + 4];
#pragma unroll
        for (int i = 0; i < 4; i++) {
            acc[i][0] = add2(acc[i][0], b0.x);
            acc[i][1] = add2(acc[i][1], b0.y);
            acc[i][2] = add2(acc[i][2], b1v.x);
            acc[i][3] = add2(acc[i][3], b1v.y);
        }
    }
    float* C = (mode == 0) ? g_z : g_uv;
#pragma unroll
    for (int i = 0; i < 4; i++) {
        int n = nbase + ng * 4 + i;
        if (n < N) {
            *(float4*)&C[n * 64 + cg * 8]     = *(float4*)&acc[i][0];
            *(float4*)&C[n * 64 + cg * 8 + 4] = *(float4*)&acc[i][2];
        }
    }
}

// ============================================================
// 7) edge MLP, warp per dst node, 8 edges (2 quads) per iteration,
// dual prefetch — two independent u-gather wavefronts in flight.
// ============================================================
__global__ void __launch_bounds__(128)
k_edge(const float* __restrict__ Wm1, const float* __restrict__ bm1,
       const float* __restrict__ Wm2, const float* __restrict__ bm2,
       float* __restrict__ out, int N) {
    __shared__ float sg[32];
    if (threadIdx.x < 32) {
        int j = threadIdx.x;
        float acc = bm1[j];
#pragma unroll
        for (int k = 0; k < 64; k++)
            acc = fmaf(g_hdest[k], Wm1[(128 + k) * 32 + j], acc);
        sg[j] = acc;
    }
    __syncthreads();

    int warp = (blockIdx.x * blockDim.x + threadIdx.x) >> 5;
    int lane = threadIdx.x & 31;
    if (warp >= N) return;
    int dst = warp;
    int g = lane >> 3;          // edge slot 0..3 within a quad
    int l = lane & 7;           // channel block: channels [4l, 4l+4)

    float4 v4 = __ldg((const float4*)&g_uv[dst * 64 + 32 + l * 4]);
    float4 gv = *(const float4*)&sg[l * 4];
    float4 w0 = __ldg(&((const float4*)&Wm1[192 * 32])[l]);
    float4 w1 = __ldg(&((const float4*)&Wm1[193 * 32])[l]);
    float4 w2 = __ldg(&((const float4*)Wm2)[l]);
    float bm2v = bm2[0];
    float bx = v4.x + gv.x, by = v4.y + gv.y;
    float bz = v4.z + gv.z, bw = v4.w + gv.w;

    int start = g_rowptr[dst], end = g_rowptr[dst + 1];
    if (start >= end) return;
    int last = end - 1;
    int e1 = start + g;
    int e2 = start + 4 + g;
    int4 pk1 = g_epack[(e1 < end) ? e1 : last];
    int4 pk2 = g_epack[(e2 < end) ? e2 : last];
    for (int idx = start; idx < end; idx += 8) {
        bool v1 = (idx + g) < end;
        bool v2 = (idx + 4 + g) < end;
        float4 u1 = __ldg((const float4*)&g_uv[pk1.x * 64 + l * 4]);
        float4 u2 = __ldg((const float4*)&g_uv[pk2.x * 64 + l * 4]);
        float a1x = __int_as_float(pk1.z), a1y = __int_as_float(pk1.w);
        float a2x = __int_as_float(pk2.z), a2y = __int_as_float(pk2.w);
        int perm1 = pk1.y, perm2 = pk2.y;
        if (idx + 8 < end) {
            int n1 = idx + 8 + g;
            int n2 = idx + 12 + g;
            pk1 = g_epack[(n1 < end) ? n1 : last];
            pk2 = g_epack[(n2 < end) ? n2 : last];
        }

        float m0 = fmaf(a1x, w0.x, fmaf(a1y, w1.x, u1.x + bx));
        float m1 = fmaf(a1x, w0.y, fmaf(a1y, w1.y, u1.y + by));
        float m2 = fmaf(a1x, w0.z, fmaf(a1y, w1.z, u1.z + bz));
        float m3 = fmaf(a1x, w0.w, fmaf(a1y, w1.w, u1.w + bw));
        float n0 = fmaf(a2x, w0.x, fmaf(a2y, w1.x, u2.x + bx));
        float n1_ = fmaf(a2x, w0.y, fmaf(a2y, w1.y, u2.y + by));
        float n2_ = fmaf(a2x, w0.z, fmaf(a2y, w1.z, u2.z + bz));
        float n3_ = fmaf(a2x, w0.w, fmaf(a2y, w1.w, u2.w + bw));
        m0 = fmaxf(m0, 0.f); m1 = fmaxf(m1, 0.f);
        m2 = fmaxf(m2, 0.f); m3 = fmaxf(m3, 0.f);
        n0 = fmaxf(n0, 0.f); n1_ = fmaxf(n1_, 0.f);
        n2_ = fmaxf(n2_, 0.f); n3_ = fmaxf(n3_, 0.f);
        float s1 = fmaf(m0, w2.x, fmaf(m1, w2.y, fmaf(m2, w2.z, m3 * w2.w)));
        float s2 = fmaf(n0, w2.x, fmaf(n1_, w2.y, fmaf(n2_, w2.z, n3_ * w2.w)));
#pragma unroll
        for (int o = 4; o >= 1; o >>= 1) {
            s1 += __shfl_xor_sync(0xffffffffu, s1, o);
            s2 += __shfl_xor_sync(0xffffffffu, s2, o);
        }
        if (l == 0) {
            if (v1) out[perm1] = s1 + bm2v;
            if (v2) out[perm2] = s2 + bm2v;
        }
    }
}

// ============================================================
extern "C" void kernel_launch(void* const* d_in, const int* in_sizes, int n_in,
                              void* d_out, int out_size) {
    const float* x     = (const float*)d_in[0];
    const int*   ei    = (const int*)d_in[1];
    const float* ea    = (const float*)d_in[2];
    const int*   dest  = (const int*)d_in[3];
    const float* W0    = (const float*)d_in[4];
    const float* b0    = (const float*)d_in[5];
    const float* We0   = (const float*)d_in[6];
    const float* att0  = (const float*)d_in[7];
    const float* bias0 = (const float*)d_in[8];
    const float* W1    = (const float*)d_in[9];
    const float* b1    = (const float*)d_in[10];
    const float* We1   = (const float*)d_in[11];
    const float* att1  = (const float*)d_in[12];
    const float* bias1 = (const float*)d_in[13];
    const float* Wm1   = (const float*)d_in[14];
    const float* bm1   = (const float*)d_in[15];
    const float* Wm2   = (const float*)d_in[16];
    const float* bm2   = (const float*)d_in[17];

    int N = in_sizes[0] / 2;
    int E = in_sizes[1] / 2;

    const int TB = 256;
    int gE    = (E + TB - 1) / TB;
    int gN    = (N + TB - 1) / TB;
    int gN8   = (N * 8 + TB - 1) / TB;
    int gAgg  = (N * 32 + 127) / 128;   // 128-thread blocks, warp per dst
    int gGemv = (N + 63) / 64;
    int nSB   = (N + 255) / 256;

    k_easum_hist_z0<<<512 + gN8, TB>>>(ei, (const float2*)ea,
                                       (const float2*)x, W0, b0, N, E);  // 0
    k_scan<<<nSB, 256>>>(N, E);                                          // 1
    k_scatter<<<gE + gN, TB>>>(ei, (const float2*)ea, N, E, gE);         // 2
    // layer 0
    k_agg<<<gAgg, 128>>>(We0, att0, bias0, (const int*)0, N);            // 3
    k_gemv<<<gGemv, 128>>>(W1, b1, N, 0);                                // 4
    // layer 1
    k_agg<<<gAgg, 128>>>(We1, att1, bias1, dest, N);                     // 5
    k_gemv<<<gGemv, 128>>>(Wm1, (const float*)0, N, 1);                  // 6
    // edge scoring head
    k_edge<<<gAgg, 128>>>(Wm1, bm1, Wm2, bm2, (float*)d_out, N);         // 7
}